// round 1
// baseline (speedup 1.0000x reference)
#include <cuda_runtime.h>

#define NN   50000
#define EE   1600000
#define C    128
#define TE   64          // edges per block in edge kernel
#define TN   64          // nodes per block in node gemm

// Scratch (device globals — no allocation allowed)
__device__ float g_T[(size_t)NN * C];   // x @ W1[:128] + b1
__device__ float g_R[(size_t)NN * C];   // x @ Wr + br
__device__ float g_M[(size_t)NN * C];   // running segment max (float bits)

__device__ __forceinline__ void atomicMaxFloat(float* addr, float v) {
    // Standard monotonic trick: works for mixed signs and -inf init.
    if (v >= 0.0f) atomicMax((int*)addr, __float_as_int(v));
    else           atomicMin((unsigned int*)addr, __float_as_uint(v));
}

// ---------------------------------------------------------------------------
__global__ void __launch_bounds__(256) init_max_kernel(int n4) {
    int i = blockIdx.x * blockDim.x + threadIdx.x;
    if (i < n4) {
        float ni = __int_as_float(0xff800000);
        ((float4*)g_M)[i] = make_float4(ni, ni, ni, ni);
    }
}

// ---------------------------------------------------------------------------
// C[row][col] = sum_k X[row][k] * W[k][col] + bias[col]   (K = C = 128)
// which == 0 -> g_T, which == 1 -> g_R
__global__ void __launch_bounds__(256, 2) node_gemm_kernel(
    const float* __restrict__ X, const float* __restrict__ W,
    const float* __restrict__ bias, int which, int nrows)
{
    extern __shared__ float sh[];
    float* Ws = sh;            // 128*128
    float* Xs = sh + C * C;    // TN*128

    const int tid  = threadIdx.x;
    const int row0 = blockIdx.x * TN;

    const float4* W4  = (const float4*)W;
    float4*       Ws4 = (float4*)Ws;
#pragma unroll
    for (int i = 0; i < 16; ++i) Ws4[tid + i * 256] = W4[tid + i * 256];

    int nrow = nrows - row0; if (nrow > TN) nrow = TN;
    const float4* X4  = (const float4*)(X + (size_t)row0 * C);
    float4*       Xs4 = (float4*)Xs;
    for (int i = tid; i < nrow * (C / 4); i += 256) Xs4[i] = X4[i];
    __syncthreads();

    const int tcol = (tid & 15) * 8;   // 16 col groups of 8
    const int trow = (tid >> 4) * 4;   // 16 row groups of 4

    float acc[4][8];
#pragma unroll
    for (int i = 0; i < 4; ++i)
#pragma unroll
        for (int j = 0; j < 8; ++j) acc[i][j] = 0.0f;

    const float* h0 = Xs + (trow + 0) * C;
    const float* h1 = Xs + (trow + 1) * C;
    const float* h2 = Xs + (trow + 2) * C;
    const float* h3 = Xs + (trow + 3) * C;

#pragma unroll 4
    for (int k = 0; k < C; ++k) {
        float a[4] = { h0[k], h1[k], h2[k], h3[k] };
        float4 w0 = *(const float4*)(Ws + k * C + tcol);
        float4 w1 = *(const float4*)(Ws + k * C + tcol + 4);
        float w[8] = { w0.x, w0.y, w0.z, w0.w, w1.x, w1.y, w1.z, w1.w };
#pragma unroll
        for (int i = 0; i < 4; ++i)
#pragma unroll
            for (int j = 0; j < 8; ++j) acc[i][j] = fmaf(a[i], w[j], acc[i][j]);
    }

    float4 bb0 = ((const float4*)bias)[tcol >> 2];
    float4 bb1 = ((const float4*)bias)[(tcol >> 2) + 1];
    float bv[8] = { bb0.x, bb0.y, bb0.z, bb0.w, bb1.x, bb1.y, bb1.z, bb1.w };

    float* dst = which ? g_R : g_T;
#pragma unroll
    for (int i = 0; i < 4; ++i) {
        int r = row0 + trow + i;
        if (r < nrows) {
            float4 o0 = make_float4(acc[i][0] + bv[0], acc[i][1] + bv[1],
                                    acc[i][2] + bv[2], acc[i][3] + bv[3]);
            float4 o1 = make_float4(acc[i][4] + bv[4], acc[i][5] + bv[5],
                                    acc[i][6] + bv[6], acc[i][7] + bv[7]);
            *(float4*)(dst + (size_t)r * C + tcol)     = o0;
            *(float4*)(dst + (size_t)r * C + tcol + 4) = o1;
        }
    }
}

// ---------------------------------------------------------------------------
// Per-edge: h1 = relu(T[row] + rel @ W1p);  h2 = h1 @ W2 + b2;  atomicMax into g_M[col]
#define H1STRIDE 132
__global__ void __launch_bounds__(256, 2) edge_kernel(
    const float* __restrict__ pos, const int* __restrict__ eidx,
    const float* __restrict__ W1, const float* __restrict__ W2,
    const float* __restrict__ b2, int E)
{
    extern __shared__ float sh[];
    float* W2s = sh;             // 128*128
    float* H1s = sh + C * C;     // TE * H1STRIDE
    __shared__ float W1p[3 * C];
    __shared__ int   s_col[TE];

    const int tid = threadIdx.x;

    const float4* W24  = (const float4*)W2;
    float4*       W2s4 = (float4*)W2s;
#pragma unroll
    for (int i = 0; i < 16; ++i) W2s4[tid + i * 256] = W24[tid + i * 256];
    if (tid < 96) ((float4*)W1p)[tid] = ((const float4*)(W1 + C * C))[tid];
    __syncthreads();

    const int e0   = blockIdx.x * TE;
    const int wid  = tid >> 5;
    const int lane = tid & 31;
    const int ch   = lane * 4;

    // Per-lane position weights (hoisted: channel is fixed per lane)
    float4 wpx = *(const float4*)&W1p[ch];
    float4 wpy = *(const float4*)&W1p[C + ch];
    float4 wpz = *(const float4*)&W1p[2 * C + ch];

#pragma unroll
    for (int j = 0; j < 8; ++j) {
        int el = wid * 8 + j;
        int e  = e0 + el;
        if (e < E) {
            int r    = eidx[e];
            int cdst = eidx[E + e];
            if (lane == 0) s_col[el] = cdst;
            float px = pos[r * 3 + 0] - pos[cdst * 3 + 0];
            float py = pos[r * 3 + 1] - pos[cdst * 3 + 1];
            float pz = pos[r * 3 + 2] - pos[cdst * 3 + 2];
            float4 t = ((const float4*)(g_T + (size_t)r * C))[lane];
            float4 h;
            h.x = fmaxf(t.x + px * wpx.x + py * wpy.x + pz * wpz.x, 0.0f);
            h.y = fmaxf(t.y + px * wpx.y + py * wpy.y + pz * wpz.y, 0.0f);
            h.z = fmaxf(t.z + px * wpx.z + py * wpy.z + pz * wpz.z, 0.0f);
            h.w = fmaxf(t.w + px * wpx.w + py * wpy.w + pz * wpz.w, 0.0f);
            *(float4*)(H1s + el * H1STRIDE + ch) = h;
        } else {
            if (lane == 0) s_col[el] = -1;
            *(float4*)(H1s + el * H1STRIDE + ch) = make_float4(0, 0, 0, 0);
        }
    }
    __syncthreads();

    const int tcol = (tid & 15) * 8;
    const int te   = (tid >> 4) * 4;

    float acc[4][8];
#pragma unroll
    for (int i = 0; i < 4; ++i)
#pragma unroll
        for (int j = 0; j < 8; ++j) acc[i][j] = 0.0f;

    const float* h0 = H1s + (te + 0) * H1STRIDE;
    const float* h1 = H1s + (te + 1) * H1STRIDE;
    const float* h2 = H1s + (te + 2) * H1STRIDE;
    const float* h3 = H1s + (te + 3) * H1STRIDE;

#pragma unroll 4
    for (int k = 0; k < C; ++k) {
        float a[4] = { h0[k], h1[k], h2[k], h3[k] };
        float4 w0 = *(const float4*)(W2s + k * C + tcol);
        float4 w1 = *(const float4*)(W2s + k * C + tcol + 4);
        float w[8] = { w0.x, w0.y, w0.z, w0.w, w1.x, w1.y, w1.z, w1.w };
#pragma unroll
        for (int i = 0; i < 4; ++i)
#pragma unroll
            for (int j = 0; j < 8; ++j) acc[i][j] = fmaf(a[i], w[j], acc[i][j]);
    }

    float4 bb0 = ((const float4*)b2)[tcol >> 2];
    float4 bb1 = ((const float4*)b2)[(tcol >> 2) + 1];
    float bv[8] = { bb0.x, bb0.y, bb0.z, bb0.w, bb1.x, bb1.y, bb1.z, bb1.w };

#pragma unroll
    for (int i = 0; i < 4; ++i) {
        int cdst = s_col[te + i];
        if (cdst < 0) continue;
        float* dst = g_M + (size_t)cdst * C + tcol;
        // Guard loads: g_M is monotone non-decreasing, so a stale read only
        // causes a redundant atomic, never a missed update.
        float4 c0 = *(const float4*)dst;
        float4 c1 = *(const float4*)(dst + 4);
        float cur[8] = { c0.x, c0.y, c0.z, c0.w, c1.x, c1.y, c1.z, c1.w };
#pragma unroll
        for (int j = 0; j < 8; ++j) {
            float v = acc[i][j] + bv[j];
            if (v > cur[j]) atomicMaxFloat(dst + j, v);
        }
    }
}

// ---------------------------------------------------------------------------
__global__ void __launch_bounds__(256) finalize_kernel(float* __restrict__ out, int n4) {
    int i = blockIdx.x * blockDim.x + threadIdx.x;
    if (i < n4) {
        float ni = __int_as_float(0xff800000);
        float4 m = ((const float4*)g_M)[i];
        float4 r = ((const float4*)g_R)[i];
        m.x = (m.x == ni) ? 0.0f : m.x;
        m.y = (m.y == ni) ? 0.0f : m.y;
        m.z = (m.z == ni) ? 0.0f : m.z;
        m.w = (m.w == ni) ? 0.0f : m.w;
        ((float4*)out)[i] = make_float4(m.x + r.x, m.y + r.y, m.z + r.z, m.w + r.w);
    }
}

// ---------------------------------------------------------------------------
extern "C" void kernel_launch(void* const* d_in, const int* in_sizes, int n_in,
                              void* d_out, int out_size) {
    const float* x    = (const float*)d_in[0];
    const float* pos  = (const float*)d_in[1];
    const int*   eidx = (const int*)d_in[2];
    const float* W1   = (const float*)d_in[3];
    const float* b1   = (const float*)d_in[4];
    const float* W2   = (const float*)d_in[5];
    const float* b2   = (const float*)d_in[6];
    const float* Wr   = (const float*)d_in[7];
    const float* br   = (const float*)d_in[8];
    float* out = (float*)d_out;

    const int nnodes = in_sizes[0] / C;          // 50000
    const int E      = in_sizes[2] / 2;          // 1600000

    const int node_smem = (C * C + TN * C) * 4;                 // 96 KB
    const int edge_smem = (C * C + TE * H1STRIDE) * 4;          // ~97 KB
    cudaFuncSetAttribute(node_gemm_kernel, cudaFuncAttributeMaxDynamicSharedMemorySize, node_smem);
    cudaFuncSetAttribute(edge_kernel,      cudaFuncAttributeMaxDynamicSharedMemorySize, edge_smem);

    const int n4 = nnodes * C / 4;
    init_max_kernel<<<(n4 + 255) / 256, 256>>>(n4);

    const int ngrid = (nnodes + TN - 1) / TN;
    node_gemm_kernel<<<ngrid, 256, node_smem>>>(x, W1, b1, 0, nnodes);  // g_T
    node_gemm_kernel<<<ngrid, 256, node_smem>>>(x, Wr, br, 1, nnodes);  // g_R

    const int egrid = (E + TE - 1) / TE;
    edge_kernel<<<egrid, 256, edge_smem>>>(pos, eidx, W1, W2, b2, E);

    finalize_kernel<<<(n4 + 255) / 256, 256>>>(out, n4);
}